// round 14
// baseline (speedup 1.0000x reference)
#include <cuda_runtime.h>
#include <cuda_bf16.h>

#define BB 8
#define HH 512
#define WW 512
#define NN 128
#define NBLK (BB * (HH / 32) * (WW / 128))   // 512 strip blocks (128x32 each)

#define FIXSCALE 1048576.0   // 2^20 fixed-point scale
#define CNT_ONE (1ULL << 48)
#define SUM_MASK (CNT_ONE - 1ULL)

// scratch (device globals: allocation is forbidden). zero-init; the block that
// completes each accumulator resets it to 0 for deterministic graph replay.
__device__ unsigned long long g_acc_hm;
__device__ unsigned long long g_acc_sc;

// ---------------------------------------------------------------------------
// Single kernel: per 128x32 strip. R13 lesson: the roof is the runtime-trip
// center loop (no unroll -> 3 dependent LDS + short FFMA chain per iter,
// issue stuck at 40%). Fixes: (1) centers packed float4 -> one LDS.128
// broadcast per iter; (2) per-warp segments padded to a multiple of 4 with
// never-winning dummies -> #pragma unroll 4 gives 4 independent chains.
// Prune is bit-exact (expf(arg)==0.0f for arg < -104). Fence-free fixed-point
// u64 atomic tail (arrival count in high bits of the atomic return value).
// ---------------------------------------------------------------------------
__global__ void __launch_bounds__(256) gt_kernel(const float* __restrict__ hm,
                                                 const float* __restrict__ sm,
                                                 const float* __restrict__ mask,
                                                 const float* __restrict__ gr,
                                                 const int* __restrict__ centers,
                                                 float* __restrict__ out) {
    __shared__ float4 s_ctr[NN];          // {cy, cx, inv, 0} per center
    __shared__ int s_wcnt[4];             // per-warp kept count, padded to %4
    __shared__ float sh_hm[8], sh_sc[8];

    const int b = blockIdx.z;
    const int y0 = blockIdx.y * 32;
    const int x0 = blockIdx.x * 128;
    const int t = threadIdx.x;
    const int lane = t & 31, wid = t >> 5;

    const int xo = (t & 7) << 2;          // 0..28 within a subtile
    const int y = y0 + (t >> 3);
    const long rowbase = (long)b * HH * WW + (long)y * WW;

    // --- issue subtile 0 bulk loads FIRST: independent of the prune, they
    // overlap the scattered center-gather latency below.
    const long a0 = rowbase + x0 + xo;
    float4 h_cur = *(const float4*)(hm + a0);
    float4 s_cur = *(const float4*)(sm + a0);
    float4 m_cur = *(const float4*)(mask + a0);

    // --- prune (warps 0-3), ballot compaction + pad-to-4 with dummies.
    if (t < NN) {
        const int2 c = ((const int2*)centers)[b * NN + t];
        const int c0 = min(max(c.x, 0), HH - 1);
        const int c1 = min(max(c.y, 0), WW - 1);
        const float s = __ldg(sm + (long)b * HH * WW + c0 * WW + c1);
        const float g = gr[b];
        // sigma = PR_MIN/gr + relu(sm)*REF_GROUND_RES/gr   (both = 0.2)
        const float sigma = 0.2f / g + fmaxf(s, 0.0f) * 0.2f / g;
        const float inv = -1.0f / (2.0f * sigma * sigma);
        const float cy = (float)c0, cx = (float)c1;
        float dy = fmaxf(fmaxf((float)y0 - cy, cy - (float)(y0 + 31)), 0.0f);
        float dx = fmaxf(fmaxf((float)x0 - cx, cx - (float)(x0 + 127)), 0.0f);
        float mind2 = fmaf(dy, dy, dx * dx);
        const bool keep = (mind2 * inv >= -104.0f);
        const unsigned ball = __ballot_sync(0xFFFFFFFFu, keep);
        const int cnt = __popc(ball);
        const int rounded = min(32, (cnt + 3) & ~3);
        if (keep) {
            int pos = __popc(ball & ((1u << lane) - 1u));
            s_ctr[wid * 32 + pos] = make_float4(cy, cx, inv, 0.0f);
        } else {
            // dummy: arg ~ -2e16, never wins the max, no NaN possible
            int npos = __popc(~ball & ((1u << lane) - 1u));
            int tgt = cnt + npos;
            if (tgt < rounded)
                s_ctr[wid * 32 + tgt] = make_float4(-1.0e8f, -1.0e8f, -1.0f, 0.0f);
        }
        if (lane == 0) s_wcnt[wid] = rounded;
    }
    __syncthreads();

    const int cn0 = s_wcnt[0], cn1 = s_wcnt[1], cn2 = s_wcnt[2], cn3 = s_wcnt[3];
    const float yf = (float)y;

    float hm_acc = 0.0f, sc_acc = 0.0f;

    #pragma unroll
    for (int st = 0; st < 4; st++) {
        // prefetch next subtile while computing this one
        float4 h_nxt, s_nxt, m_nxt;
        if (st < 3) {
            const long an = rowbase + x0 + (st + 1) * 32 + xo;
            h_nxt = *(const float4*)(hm + an);
            s_nxt = *(const float4*)(sm + an);
            m_nxt = *(const float4*)(mask + an);
        }

        const int x = x0 + st * 32 + xo;
        const float xf0 = (float)x, xf1 = xf0 + 1.0f, xf2 = xf0 + 2.0f, xf3 = xf0 + 3.0f;
        float best0 = -3.0e38f, best1 = -3.0e38f, best2 = -3.0e38f, best3 = -3.0e38f;

        #pragma unroll
        for (int w4 = 0; w4 < 4; w4++) {
            const int cend = (w4 == 0) ? cn0 : (w4 == 1) ? cn1 : (w4 == 2) ? cn2 : cn3;
            #pragma unroll 4
            for (int i = 0; i < cend; i++) {
                const float4 c = s_ctr[w4 * 32 + i];   // one LDS.128 broadcast
                const float dy = yf - c.x;
                const float dy2 = dy * dy;
                const float dx0 = xf0 - c.y, dx1 = xf1 - c.y,
                            dx2 = xf2 - c.y, dx3 = xf3 - c.y;
                best0 = fmaxf(best0, fmaf(dx0, dx0, dy2) * c.z);
                best1 = fmaxf(best1, fmaf(dx1, dx1, dy2) * c.z);
                best2 = fmaxf(best2, fmaf(dx2, dx2, dy2) * c.z);
                best3 = fmaxf(best3, fmaf(dx3, dx3, dy2) * c.z);
            }
        }

        const float g0 = __expf(best0);   // underflows to exact 0 when no center
        const float g1 = __expf(best1);
        const float g2 = __expf(best2);
        const float g3 = __expf(best3);

        // gt output lives at out+2 -> only 8B aligned; float2 stores
        float* gout = out + 2 + rowbase + x;
        *(float2*)(gout) = make_float2(g0, g1);
        *(float2*)(gout + 2) = make_float2(g2, g3);

        const float d0 = h_cur.x - g0, d1 = h_cur.y - g1,
                    d2 = h_cur.z - g2, d3 = h_cur.w - g3;
        hm_acc += d0 * d0 * m_cur.x + d1 * d1 * m_cur.y +
                  d2 * d2 * m_cur.z + d3 * d3 * m_cur.w;
        sc_acc += s_cur.x * s_cur.x + s_cur.y * s_cur.y +
                  s_cur.z * s_cur.z + s_cur.w * s_cur.w;

        h_cur = h_nxt; s_cur = s_nxt; m_cur = m_nxt;
    }

    // --- block reduction
    #pragma unroll
    for (int o = 16; o; o >>= 1) {
        hm_acc += __shfl_down_sync(0xFFFFFFFFu, hm_acc, o);
        sc_acc += __shfl_down_sync(0xFFFFFFFFu, sc_acc, o);
    }
    if (lane == 0) {
        sh_hm[wid] = hm_acc;
        sh_sc[wid] = sc_acc;
    }
    __syncthreads();

    if (t == 0) {
        double ah = 0.0, as = 0.0;
        #pragma unroll
        for (int k = 0; k < 8; k++) {
            ah += (double)sh_hm[k];
            as += (double)sh_sc[k];
        }
        // quantize block partials to 2^-20 fixed point; pack +1 into bits[48:64)
        const unsigned long long vh =
            (unsigned long long)(ah * FIXSCALE + 0.5) | CNT_ONE;
        const unsigned long long vs =
            (unsigned long long)(as * FIXSCALE + 0.5) | CNT_ONE;
        const unsigned long long rh = atomicAdd(&g_acc_hm, vh);
        const unsigned long long rs = atomicAdd(&g_acc_sc, vs);

        const double invn = 1.0 / ((double)BB * HH * WW * FIXSCALE);
        if ((rh >> 48) == NBLK - 1u) {            // I completed the hm sum
            const unsigned long long tot = (rh + vh) & SUM_MASK;
            out[1] = (float)((double)tot * invn);
            g_acc_hm = 0ULL;                      // reset for graph replay
        }
        if ((rs >> 48) == NBLK - 1u) {            // I completed the sc sum
            const unsigned long long tot = (rs + vs) & SUM_MASK;
            out[0] = (float)((double)tot * invn);
            g_acc_sc = 0ULL;                      // reset for graph replay
        }
    }
}

extern "C" void kernel_launch(void* const* d_in, const int* in_sizes, int n_in,
                              void* d_out, int out_size) {
    const float* hm = (const float*)d_in[0];       // pred_hm [8,1,512,512]
    const float* sm = (const float*)d_in[1];       // pred_sm [8,1,512,512]
    const float* gr = (const float*)d_in[2];       // ground_resolution [8]
    const float* mask = (const float*)d_in[3];     // mask [8,1,512,512]
    const int* centers = (const int*)d_in[4];      // centers [8,128,2]
    float* out = (float*)d_out;                    // [scale_loss, hm_loss, gts...]

    dim3 grid(WW / 128, HH / 32, BB);              // 4 x 16 x 8 = 512
    gt_kernel<<<grid, 256>>>(hm, sm, mask, gr, centers, out);
}

// round 15
// speedup vs baseline: 1.1629x; 1.1629x over previous
#include <cuda_runtime.h>
#include <cuda_bf16.h>

#define BB 8
#define HH 512
#define WW 512
#define NN 128
#define NBLK (BB * (HH / 32) * (WW / 128))   // 512 strip blocks (128x32 each)

#define FIXSCALE 1048576.0   // 2^20 fixed-point scale
#define CNT_ONE (1ULL << 48)
#define SUM_MASK (CNT_ONE - 1ULL)

// scratch (device globals: allocation is forbidden). zero-init; the block that
// completes each accumulator resets it to 0 for deterministic graph replay.
__device__ unsigned long long g_acc_hm;
__device__ unsigned long long g_acc_sc;

// ---------------------------------------------------------------------------
// Single kernel, per 128x32 strip. R14 lesson: instruction-count-bound; the
// per-warp-segment padding ran ~16 iters/subtile where ~2.5 suffice. Fixes:
//  - prune per 32x32 SUBTILE (4 compact lists built in ONE phase/barrier via
//    ballot + shared atomicAdd), so each list only holds centers within reach
//    of that 32-wide column;
//  - NO padding: idx = min(i+j, cnt-1) — duplicates are idempotent under max,
//    so the x4 unroll has zero dummy work and zero guards.
// Prune is bit-exact (expf(arg)==0.0f for arg < -104). Fence-free fixed-point
// u64 atomic tail (arrival count in high bits of the atomic return value).
// ---------------------------------------------------------------------------
__global__ void __launch_bounds__(256) gt_kernel(const float* __restrict__ hm,
                                                 const float* __restrict__ sm,
                                                 const float* __restrict__ mask,
                                                 const float* __restrict__ gr,
                                                 const int* __restrict__ centers,
                                                 float* __restrict__ out) {
    __shared__ float4 s_ctr[4][NN];       // per-subtile compacted {cy,cx,inv,0}
    __shared__ int s_cnt4[4];             // per-subtile kept counts
    __shared__ float sh_hm[8], sh_sc[8];

    const int b = blockIdx.z;
    const int y0 = blockIdx.y * 32;
    const int x0 = blockIdx.x * 128;
    const int t = threadIdx.x;
    const int lane = t & 31, wid = t >> 5;

    const int xo = (t & 7) << 2;          // 0..28 within a subtile
    const int y = y0 + (t >> 3);
    const long rowbase = (long)b * HH * WW + (long)y * WW;

    // --- issue subtile 0 bulk loads FIRST (overlap the gather + prune below)
    const long a0 = rowbase + x0 + xo;
    float4 h_cur = *(const float4*)(hm + a0);
    float4 s_cur = *(const float4*)(sm + a0);
    float4 m_cur = *(const float4*)(mask + a0);

    if (t < 4) s_cnt4[t] = 0;
    __syncthreads();

    // --- one phase: compute params (registers) + prune vs EACH subtile
    if (t < NN) {
        const int2 c = ((const int2*)centers)[b * NN + t];
        const int c0 = min(max(c.x, 0), HH - 1);
        const int c1 = min(max(c.y, 0), WW - 1);
        const float s = __ldg(sm + (long)b * HH * WW + c0 * WW + c1);
        const float g = gr[b];
        // sigma = PR_MIN/gr + relu(sm)*REF_GROUND_RES/gr   (both = 0.2)
        const float sigma = 0.2f / g + fmaxf(s, 0.0f) * 0.2f / g;
        const float inv = -1.0f / (2.0f * sigma * sigma);
        const float cy = (float)c0, cx = (float)c1;
        const float dyw = fmaxf(fmaxf((float)y0 - cy, cy - (float)(y0 + 31)), 0.0f);
        const float dy2w = dyw * dyw;

        #pragma unroll
        for (int st = 0; st < 4; st++) {
            const float xs = (float)(x0 + st * 32);
            const float dxw = fmaxf(fmaxf(xs - cx, cx - (xs + 31.0f)), 0.0f);
            const bool keep = (fmaf(dxw, dxw, dy2w) * inv >= -104.0f);
            const unsigned ball = __ballot_sync(0xFFFFFFFFu, keep);
            int base = 0;
            if (lane == 0 && ball)
                base = atomicAdd(&s_cnt4[st], __popc(ball));
            base = __shfl_sync(0xFFFFFFFFu, base, 0);
            if (keep) {
                const int pos = base + __popc(ball & ((1u << lane) - 1u));
                s_ctr[st][pos] = make_float4(cy, cx, inv, 0.0f);
            }
        }
    }
    __syncthreads();

    const float yf = (float)y;
    float hm_acc = 0.0f, sc_acc = 0.0f;

    #pragma unroll
    for (int st = 0; st < 4; st++) {
        // prefetch next subtile while computing this one
        float4 h_nxt, s_nxt, m_nxt;
        if (st < 3) {
            const long an = rowbase + x0 + (st + 1) * 32 + xo;
            h_nxt = *(const float4*)(hm + an);
            s_nxt = *(const float4*)(sm + an);
            m_nxt = *(const float4*)(mask + an);
        }

        const int x = x0 + st * 32 + xo;
        const float xf0 = (float)x, xf1 = xf0 + 1.0f, xf2 = xf0 + 2.0f, xf3 = xf0 + 3.0f;
        float best0 = -3.0e38f, best1 = -3.0e38f, best2 = -3.0e38f, best3 = -3.0e38f;

        const int cnt = s_cnt4[st];
        const int cnt1 = cnt - 1;
        const int rounded = (cnt + 3) & ~3;
        for (int i = 0; i < rounded; i += 4) {
            #pragma unroll
            for (int j = 0; j < 4; j++) {
                const int idx = min(i + j, cnt1);      // clamp: dup = no-op for max
                const float4 c = s_ctr[st][idx];       // LDS.128 broadcast
                const float dy = yf - c.x;
                const float dy2 = dy * dy;
                const float dx0 = xf0 - c.y, dx1 = xf1 - c.y,
                            dx2 = xf2 - c.y, dx3 = xf3 - c.y;
                best0 = fmaxf(best0, fmaf(dx0, dx0, dy2) * c.z);
                best1 = fmaxf(best1, fmaf(dx1, dx1, dy2) * c.z);
                best2 = fmaxf(best2, fmaf(dx2, dx2, dy2) * c.z);
                best3 = fmaxf(best3, fmaf(dx3, dx3, dy2) * c.z);
            }
        }

        const float g0 = __expf(best0);   // underflows to exact 0 when no center
        const float g1 = __expf(best1);
        const float g2 = __expf(best2);
        const float g3 = __expf(best3);

        // gt output lives at out+2 -> only 8B aligned; float2 stores
        float* gout = out + 2 + rowbase + x;
        *(float2*)(gout) = make_float2(g0, g1);
        *(float2*)(gout + 2) = make_float2(g2, g3);

        const float d0 = h_cur.x - g0, d1 = h_cur.y - g1,
                    d2 = h_cur.z - g2, d3 = h_cur.w - g3;
        hm_acc += d0 * d0 * m_cur.x + d1 * d1 * m_cur.y +
                  d2 * d2 * m_cur.z + d3 * d3 * m_cur.w;
        sc_acc += s_cur.x * s_cur.x + s_cur.y * s_cur.y +
                  s_cur.z * s_cur.z + s_cur.w * s_cur.w;

        h_cur = h_nxt; s_cur = s_nxt; m_cur = m_nxt;
    }

    // --- block reduction
    #pragma unroll
    for (int o = 16; o; o >>= 1) {
        hm_acc += __shfl_down_sync(0xFFFFFFFFu, hm_acc, o);
        sc_acc += __shfl_down_sync(0xFFFFFFFFu, sc_acc, o);
    }
    if (lane == 0) {
        sh_hm[wid] = hm_acc;
        sh_sc[wid] = sc_acc;
    }
    __syncthreads();

    if (t == 0) {
        double ah = 0.0, as = 0.0;
        #pragma unroll
        for (int k = 0; k < 8; k++) {
            ah += (double)sh_hm[k];
            as += (double)sh_sc[k];
        }
        // quantize block partials to 2^-20 fixed point; pack +1 into bits[48:64)
        const unsigned long long vh =
            (unsigned long long)(ah * FIXSCALE + 0.5) | CNT_ONE;
        const unsigned long long vs =
            (unsigned long long)(as * FIXSCALE + 0.5) | CNT_ONE;
        const unsigned long long rh = atomicAdd(&g_acc_hm, vh);
        const unsigned long long rs = atomicAdd(&g_acc_sc, vs);

        const double invn = 1.0 / ((double)BB * HH * WW * FIXSCALE);
        if ((rh >> 48) == NBLK - 1u) {            // I completed the hm sum
            const unsigned long long tot = (rh + vh) & SUM_MASK;
            out[1] = (float)((double)tot * invn);
            g_acc_hm = 0ULL;                      // reset for graph replay
        }
        if ((rs >> 48) == NBLK - 1u) {            // I completed the sc sum
            const unsigned long long tot = (rs + vs) & SUM_MASK;
            out[0] = (float)((double)tot * invn);
            g_acc_sc = 0ULL;                      // reset for graph replay
        }
    }
}

extern "C" void kernel_launch(void* const* d_in, const int* in_sizes, int n_in,
                              void* d_out, int out_size) {
    const float* hm = (const float*)d_in[0];       // pred_hm [8,1,512,512]
    const float* sm = (const float*)d_in[1];       // pred_sm [8,1,512,512]
    const float* gr = (const float*)d_in[2];       // ground_resolution [8]
    const float* mask = (const float*)d_in[3];     // mask [8,1,512,512]
    const int* centers = (const int*)d_in[4];      // centers [8,128,2]
    float* out = (float*)d_out;                    // [scale_loss, hm_loss, gts...]

    dim3 grid(WW / 128, HH / 32, BB);              // 4 x 16 x 8 = 512
    gt_kernel<<<grid, 256>>>(hm, sm, mask, gr, centers, out);
}